// round 2
// baseline (speedup 1.0000x reference)
#include <cuda_runtime.h>

#define Bz  8
#define Nn  8192
#define Dm  256
#define Hh  4
#define Rr  64
#define HDd 64
#define Mm  (Bz*Nn)          // 65536 rows
#define NITER 8              // row-tiles (64 rows) per kattn block

// ---------- scratch (device globals: allocation-free) ----------
__device__ float g_WK[Dm*Dm];                 // folded Wq @ K^T / 8
__device__ float g_bK[Dm];                    // folded bias
__device__ float g_xv[(size_t)Mm*Dm];         // x @ Wv + bv           (64 MB)
__device__ float g_e [(size_t)Mm*Dm];         // exp(attn)             (64 MB)
__device__ float g_pool[Bz*Hh*Rr*HDd];        // pooled (later *1/S)   (512 KB)
__device__ float g_S [Bz*Hh*Rr];              // sum_n e

// ---------- zero accumulators ----------
__global__ void kzero() {
    int i = blockIdx.x*blockDim.x + threadIdx.x;
    if (i < Bz*Hh*Rr*HDd) g_pool[i] = 0.f;
    if (i < Bz*Hh*Rr)     g_S[i]   = 0.f;
}

// ---------- fold Wq and K into WK (and bq into bK) ----------
__global__ void kprep(const float* __restrict__ Wq, const float* __restrict__ bq,
                      const float* __restrict__ K) {
    int col = threadIdx.x;                // 0..255  = h*64 + r
    int h = col >> 6, r = col & 63;
    const float* Krow = K + r*Dm + h*HDd; // K[(r*H + h)*64 + d]
    if (blockIdx.x < Dm) {
        int c = blockIdx.x;
        const float* wq = Wq + c*Dm + h*HDd;
        float s = 0.f;
        #pragma unroll 16
        for (int d = 0; d < HDd; d++) s = fmaf(wq[d], Krow[d], s);
        g_WK[c*Dm + col] = 0.125f * s;
    } else {
        float s = 0.f;
        #pragma unroll 16
        for (int d = 0; d < HDd; d++) s = fmaf(bq[h*HDd + d], Krow[d], s);
        g_bK[col] = 0.125f * s;
    }
}

// ---------- xv = x @ Wv + bv  (64x64 tile SGEMM, 4x4/thread) ----------
__global__ void kgemm_xv(const float* __restrict__ A, const float* __restrict__ W,
                         const float* __restrict__ bias) {
    __shared__ float As[16][68];   // [k][m] transposed
    __shared__ float Ws[16][68];   // [k][n]
    int t  = threadIdx.x;
    int m0 = blockIdx.x * 64, n0 = blockIdx.y * 64;
    int ty = t >> 4, tx = t & 15;
    int lrow = t >> 2, lkq = t & 3;     // A loader
    int lkk  = t >> 4, lj4 = t & 15;    // W loader
    float acc[4][4] = {};
    for (int k0 = 0; k0 < Dm; k0 += 16) {
        float4 av = *(const float4*)(A + (size_t)(m0 + lrow)*Dm + k0 + lkq*4);
        float4 wv = *(const float4*)(W + (size_t)(k0 + lkk)*Dm + n0 + lj4*4);
        __syncthreads();
        As[lkq*4+0][lrow] = av.x; As[lkq*4+1][lrow] = av.y;
        As[lkq*4+2][lrow] = av.z; As[lkq*4+3][lrow] = av.w;
        *(float4*)&Ws[lkk][lj4*4] = wv;
        __syncthreads();
        #pragma unroll
        for (int kk = 0; kk < 16; kk++) {
            float4 a = *(const float4*)&As[kk][ty*4];
            float4 b = *(const float4*)&Ws[kk][tx*4];
            float ar[4] = {a.x, a.y, a.z, a.w};
            float br[4] = {b.x, b.y, b.z, b.w};
            #pragma unroll
            for (int i = 0; i < 4; i++)
                #pragma unroll
                for (int j = 0; j < 4; j++)
                    acc[i][j] = fmaf(ar[i], br[j], acc[i][j]);
        }
    }
    float4 bb = *(const float4*)(bias + n0 + tx*4);
    #pragma unroll
    for (int i = 0; i < 4; i++) {
        float4 o = {acc[i][0]+bb.x, acc[i][1]+bb.y, acc[i][2]+bb.z, acc[i][3]+bb.w};
        *(float4*)(g_xv + (size_t)(m0 + ty*4 + i)*Dm + n0 + tx*4) = o;
    }
}

// ---------- attn GEMM + exp + r-softmax + pooled accumulation ----------
__global__ void kattn(const float* __restrict__ Z) {
    __shared__ float Zs[16][68];
    __shared__ float Ws[16][68];
    __shared__ float Es[64][68];   // e values, then A1 (normalized)
    __shared__ float XVs[64][68];  // xv head slice
    int t = threadIdx.x;
    int h = blockIdx.y;
    int m_base = blockIdx.x * (64*NITER);
    int b = m_base / Nn;
    int ty = t >> 4, tx = t & 15;
    int lrow = t >> 2, lkq = t & 3;
    int lkk  = t >> 4, lj4 = t & 15;
    int srow = t >> 2, srq = t & 3;   // softmax mapping
    float pool[4][4] = {};
    float4 bk = *(const float4*)(g_bK + h*64 + tx*4);

    for (int it = 0; it < NITER; it++) {
        int m0 = m_base + it*64;
        float acc[4][4] = {};
        for (int k0 = 0; k0 < Dm; k0 += 16) {
            float4 av = *(const float4*)(Z + (size_t)(m0 + lrow)*Dm + k0 + lkq*4);
            float4 wv = *(const float4*)(g_WK + (size_t)(k0 + lkk)*Dm + h*64 + lj4*4);
            __syncthreads();
            Zs[lkq*4+0][lrow] = av.x; Zs[lkq*4+1][lrow] = av.y;
            Zs[lkq*4+2][lrow] = av.z; Zs[lkq*4+3][lrow] = av.w;
            *(float4*)&Ws[lkk][lj4*4] = wv;
            __syncthreads();
            #pragma unroll
            for (int kk = 0; kk < 16; kk++) {
                float4 a = *(const float4*)&Zs[kk][ty*4];
                float4 bq4 = *(const float4*)&Ws[kk][tx*4];
                float ar[4] = {a.x, a.y, a.z, a.w};
                float br[4] = {bq4.x, bq4.y, bq4.z, bq4.w};
                #pragma unroll
                for (int i = 0; i < 4; i++)
                    #pragma unroll
                    for (int j = 0; j < 4; j++)
                        acc[i][j] = fmaf(ar[i], br[j], acc[i][j]);
            }
        }
        // bias + exp; stage e to smem, stream e to global
        #pragma unroll
        for (int i = 0; i < 4; i++) {
            float4 e4;
            e4.x = __expf(acc[i][0] + bk.x);
            e4.y = __expf(acc[i][1] + bk.y);
            e4.z = __expf(acc[i][2] + bk.z);
            e4.w = __expf(acc[i][3] + bk.w);
            *(float4*)&Es[ty*4 + i][tx*4] = e4;
            *(float4*)(g_e + (size_t)(m0 + ty*4 + i)*Dm + h*64 + tx*4) = e4;
        }
        // load xv head slice for this tile
        #pragma unroll
        for (int p = 0; p < 4; p++) {
            int idx = t + p*256;
            int row = idx >> 4, d4 = idx & 15;
            *(float4*)&XVs[row][d4*4] =
                *(const float4*)(g_xv + (size_t)(m0 + row)*Dm + h*64 + d4*4);
        }
        __syncthreads();
        // r-softmax: 4 lanes/row (same warp), sum 16 each, shfl-combine, normalize
        {
            float s = 0.f;
            #pragma unroll 16
            for (int k = 0; k < 16; k++) s += Es[srow][srq*16 + k];
            s += __shfl_xor_sync(0xffffffffu, s, 1);
            s += __shfl_xor_sync(0xffffffffu, s, 2);
            float inv = 1.f / s;
            #pragma unroll 16
            for (int k = 0; k < 16; k++) Es[srow][srq*16 + k] *= inv;
        }
        __syncthreads();
        // pooled[r][d] += A1[n][r] * xv[n][d]
        #pragma unroll 4
        for (int n = 0; n < 64; n++) {
            float4 a  = *(const float4*)&Es[n][ty*4];
            float4 x4 = *(const float4*)&XVs[n][tx*4];
            float ar[4] = {a.x, a.y, a.z, a.w};
            float xr[4] = {x4.x, x4.y, x4.z, x4.w};
            #pragma unroll
            for (int i = 0; i < 4; i++)
                #pragma unroll
                for (int j = 0; j < 4; j++)
                    pool[i][j] = fmaf(ar[i], xr[j], pool[i][j]);
        }
        __syncthreads();
    }
    #pragma unroll
    for (int i = 0; i < 4; i++)
        #pragma unroll
        for (int j = 0; j < 4; j++)
            atomicAdd(&g_pool[((b*Hh + h)*Rr + ty*4 + i)*HDd + tx*4 + j], pool[i][j]);
}

// ---------- S[b,h,r] = sum_n e  (pure sum; chunked over n) ----------
#define NCH 16
__global__ void ksum() {
    int bid = blockIdx.x;
    int ch = bid & (NCH-1); int bh = bid / NCH;
    int h = bh & 3, b = bh >> 2;
    int t = threadIdx.x; int r = t & 63; int sub = t >> 6;
    int nbase = ch*(Nn/NCH) + sub*(Nn/NCH/4);
    const float* p = g_e + ((size_t)(b*Nn + nbase))*Dm + h*64 + r;
    float s = 0.f;
    #pragma unroll 8
    for (int k = 0; k < Nn/NCH/4; k++) s += p[(size_t)k*Dm];
    __shared__ float sh[256];
    sh[t] = s; __syncthreads();
    if (t < 64)
        atomicAdd(&g_S[(b*Hh + h)*64 + r], sh[t] + sh[t+64] + sh[t+128] + sh[t+192]);
}

// ---------- pooled *= 1/S ----------
__global__ void kfin() {
    int i = blockIdx.x*256 + threadIdx.x;     // 0..2047 = (b,h,r)
    float inv = 1.f / g_S[i];
    float4* p = (float4*)(g_pool + (size_t)i*HDd);
    #pragma unroll
    for (int d4 = 0; d4 < 16; d4++) {
        float4 v = p[d4];
        v.x *= inv; v.y *= inv; v.z *= inv; v.w *= inv;
        p[d4] = v;
    }
}

// ---------- redistribute + gated output ----------
#define STR 260
#define SMEM_OUT ((2*64*STR + Hh*Rr*HDd)*4)
__global__ void kout(const float* __restrict__ alpha, const float* __restrict__ beta,
                     float* __restrict__ out) {
    extern __shared__ float sm[];
    float* Es  = sm;                // 64 x 260
    float* XVs = sm + 64*STR;       // 64 x 260
    float* P2  = sm + 2*64*STR;     // [h][r][d] = 16384
    int t = threadIdx.x;
    int tile = blockIdx.x;
    int b = tile / (Nn/64);
    int n0 = (tile % (Nn/64)) * 64;
    size_t base = ((size_t)b*Nn + n0) * Dm;
    #pragma unroll
    for (int p = 0; p < 16; p++) {
        int idx = t + p*256;
        int row = idx >> 6, c4 = idx & 63;
        *(float4*)&Es [row*STR + c4*4] = *(const float4*)(g_e  + base + (size_t)row*Dm + c4*4);
        *(float4*)&XVs[row*STR + c4*4] = *(const float4*)(g_xv + base + (size_t)row*Dm + c4*4);
    }
    #pragma unroll
    for (int p = 0; p < 16; p++) {
        int idx = t + p*256;
        *(float4*)&P2[idx*4] = *(const float4*)(g_pool + (size_t)b*(Hh*Rr*HDd) + idx*4);
    }
    __syncthreads();
    int n = t & 63, h = t >> 6;
    float acc[64] = {};
    const float* Erow = Es + n*STR + h*64;
    const float* Ph = P2 + h*Rr*HDd;
    for (int r = 0; r < Rr; r++) {
        float e = Erow[r];
        const float4* pr = (const float4*)(Ph + r*HDd);
        #pragma unroll
        for (int d4 = 0; d4 < 16; d4++) {
            float4 pv = pr[d4];
            acc[d4*4+0] = fmaf(e, pv.x, acc[d4*4+0]);
            acc[d4*4+1] = fmaf(e, pv.y, acc[d4*4+1]);
            acc[d4*4+2] = fmaf(e, pv.z, acc[d4*4+2]);
            acc[d4*4+3] = fmaf(e, pv.w, acc[d4*4+3]);
        }
    }
    float sa = 1.f / (1.f + __expf(-alpha[h]));
    float sb = 1.f / (1.f + __expf(-beta[h]));
    float* op = out + base + (size_t)n*Dm + h*64;
    const float* xvp = XVs + n*STR + h*64;
    #pragma unroll
    for (int d4 = 0; d4 < 16; d4++) {
        float4 o;
        o.x = fmaf(sa, xvp[d4*4+0], sb*acc[d4*4+0]);
        o.y = fmaf(sa, xvp[d4*4+1], sb*acc[d4*4+1]);
        o.z = fmaf(sa, xvp[d4*4+2], sb*acc[d4*4+2]);
        o.w = fmaf(sa, xvp[d4*4+3], sb*acc[d4*4+3]);
        *(float4*)(op + d4*4) = o;
    }
}

extern "C" void kernel_launch(void* const* d_in, const int* in_sizes, int n_in,
                              void* d_out, int out_size) {
    const float* x     = (const float*)d_in[0];
    const float* z     = (const float*)d_in[1];
    const float* Wq    = (const float*)d_in[2];
    const float* bq    = (const float*)d_in[3];
    const float* K     = (const float*)d_in[4];
    const float* Wv    = (const float*)d_in[5];
    const float* bv    = (const float*)d_in[6];
    const float* alpha = (const float*)d_in[7];
    const float* beta  = (const float*)d_in[8];
    float* out = (float*)d_out;

    kzero<<<512, 256>>>();
    kprep<<<Dm + 1, 256>>>(Wq, bq, K);
    kgemm_xv<<<dim3(Mm/64, Dm/64), 256>>>(x, Wv, bv);
    kattn<<<dim3(Mm/(64*NITER), Hh), 256>>>(z);
    ksum<<<Bz*Hh*NCH, 256>>>();
    kfin<<<Bz*Hh*Rr/256, 256>>>();
    cudaFuncSetAttribute(kout, cudaFuncAttributeMaxDynamicSharedMemorySize, SMEM_OUT);
    kout<<<Mm/64, 256, SMEM_OUT>>>(alpha, beta, out);
}

// round 3
// speedup vs baseline: 1.3905x; 1.3905x over previous
#include <cuda_runtime.h>
#include <cstdint>

#define Bz  8
#define Nn  8192
#define Dm  256
#define Hh  4
#define Rr  64
#define HDd 64
#define Mm  (Bz*Nn)

typedef unsigned long long u64;

__device__ float g_WK[Dm*Dm];
__device__ float g_bK[Dm];
__device__ float g_xv[(size_t)Mm*Dm];
__device__ float g_e [(size_t)Mm*Dm];          // A1 (r-softmax normalized)
__device__ float g_rs[(size_t)Mm*Hh];          // raw rowsums
__device__ float g_pool[Bz*Hh*Rr*HDd];
__device__ float g_S [Bz*Hh*Rr];

__device__ __forceinline__ u64 pk2(float x, float y) {
    u64 r; asm("mov.b64 %0, {%1,%2};" : "=l"(r) : "f"(x), "f"(y)); return r;
}
__device__ __forceinline__ float2 up2(u64 v) {
    float2 f; asm("mov.b64 {%0,%1}, %2;" : "=f"(f.x), "=f"(f.y) : "l"(v)); return f;
}
#define FMA2(d,a,b) asm("fma.rn.f32x2 %0, %1, %2, %0;" : "+l"(d) : "l"(a), "l"(b))

__device__ __forceinline__ void cpa16(uint32_t d, const float* s) {
    asm volatile("cp.async.cg.shared.global [%0], [%1], 16;" :: "r"(d), "l"(s));
}
#define CPCOMMIT() asm volatile("cp.async.commit_group;")
#define CPWAIT(n)  asm volatile("cp.async.wait_group %0;" :: "n"(n))

__global__ void kzero() {
    int i = blockIdx.x*blockDim.x + threadIdx.x;
    if (i < Bz*Hh*Rr*HDd) g_pool[i] = 0.f;
    if (i < Bz*Hh*Rr)     g_S[i]   = 0.f;
}

__global__ void kprep(const float* __restrict__ Wq, const float* __restrict__ bq,
                      const float* __restrict__ K) {
    int col = threadIdx.x;
    int h = col >> 6, r = col & 63;
    const float* Krow = K + r*Dm + h*HDd;
    if (blockIdx.x < Dm) {
        int c = blockIdx.x;
        const float* wq = Wq + c*Dm + h*HDd;
        float s = 0.f;
        #pragma unroll 16
        for (int d = 0; d < HDd; d++) s = fmaf(wq[d], Krow[d], s);
        g_WK[c*Dm + col] = 0.125f * s;
    } else {
        float s = 0.f;
        #pragma unroll 16
        for (int d = 0; d < HDd; d++) s = fmaf(bq[h*HDd + d], Krow[d], s);
        g_bK[col] = 0.125f * s;
    }
}

#define AS_STRIDE 66
#define BS_STRIDE 260
#define SMEM_GEMM ((Dm*AS_STRIDE + 2*16*BS_STRIDE)*4)

#define GEMM_STAGE_A(Aptr)                                                   \
    {                                                                        \
        int r = t >> 2;                                                      \
        const float4* arow = (const float4*)((Aptr) + (size_t)(m0 + r)*Dm);  \
        _Pragma("unroll")                                                    \
        for (int c = 0; c < 16; c++) {                                       \
            float4 v = arow[c*4 + (t & 3)];                                  \
            int k0 = c*16 + (t & 3)*4;                                       \
            As[(k0+0)*AS_STRIDE + r] = v.x;                                  \
            As[(k0+1)*AS_STRIDE + r] = v.y;                                  \
            As[(k0+2)*AS_STRIDE + r] = v.z;                                  \
            As[(k0+3)*AS_STRIDE + r] = v.w;                                  \
        }                                                                    \
    }

#define GEMM_MAIN(Bptr)                                                      \
    u64 acc[4][8] = {};                                                      \
    {                                                                        \
        int brow = t >> 4, bseg = (t & 15)*4;                                \
        const float* gb = (Bptr) + (size_t)brow*Dm + bseg;                   \
        uint32_t sdst = (uint32_t)__cvta_generic_to_shared(                  \
                            Bs + brow*BS_STRIDE + bseg);                     \
        _Pragma("unroll")                                                    \
        for (int p = 0; p < 4; p++) cpa16(sdst + p*256, gb + p*64);          \
        CPCOMMIT();                                                          \
        for (int kt = 0; kt < 16; kt++) {                                    \
            if (kt < 15) {                                                   \
                const float* g2 = gb + (size_t)(kt+1)*16*Dm;                 \
                uint32_t d2 = sdst + ((kt+1)&1)*16*BS_STRIDE*4;              \
                _Pragma("unroll")                                            \
                for (int p = 0; p < 4; p++) cpa16(d2 + p*256, g2 + p*64);    \
                CPCOMMIT();                                                  \
                CPWAIT(1);                                                   \
            } else {                                                         \
                CPWAIT(0);                                                   \
            }                                                                \
            __syncthreads();                                                 \
            const float* bsk = Bs + (kt&1)*16*BS_STRIDE;                     \
            _Pragma("unroll")                                                \
            for (int kk = 0; kk < 16; kk++) {                                \
                const u64* ap = (const u64*)(As + (kt*16+kk)*AS_STRIDE + ty*8); \
                u64 a0 = ap[0], a1 = ap[1], a2 = ap[2], a3 = ap[3];          \
                const float4* bp = (const float4*)(bsk + kk*BS_STRIDE + tx*4); \
                float4 b0 = bp[0], b1 = bp[32];                              \
                u64 bb;                                                      \
                bb = pk2(b0.x,b0.x); FMA2(acc[0][0],a0,bb); FMA2(acc[1][0],a1,bb); FMA2(acc[2][0],a2,bb); FMA2(acc[3][0],a3,bb); \
                bb = pk2(b0.y,b0.y); FMA2(acc[0][1],a0,bb); FMA2(acc[1][1],a1,bb); FMA2(acc[2][1],a2,bb); FMA2(acc[3][1],a3,bb); \
                bb = pk2(b0.z,b0.z); FMA2(acc[0][2],a0,bb); FMA2(acc[1][2],a1,bb); FMA2(acc[2][2],a2,bb); FMA2(acc[3][2],a3,bb); \
                bb = pk2(b0.w,b0.w); FMA2(acc[0][3],a0,bb); FMA2(acc[1][3],a1,bb); FMA2(acc[2][3],a2,bb); FMA2(acc[3][3],a3,bb); \
                bb = pk2(b1.x,b1.x); FMA2(acc[0][4],a0,bb); FMA2(acc[1][4],a1,bb); FMA2(acc[2][4],a2,bb); FMA2(acc[3][4],a3,bb); \
                bb = pk2(b1.y,b1.y); FMA2(acc[0][5],a0,bb); FMA2(acc[1][5],a1,bb); FMA2(acc[2][5],a2,bb); FMA2(acc[3][5],a3,bb); \
                bb = pk2(b1.z,b1.z); FMA2(acc[0][6],a0,bb); FMA2(acc[1][6],a1,bb); FMA2(acc[2][6],a2,bb); FMA2(acc[3][6],a3,bb); \
                bb = pk2(b1.w,b1.w); FMA2(acc[0][7],a0,bb); FMA2(acc[1][7],a1,bb); FMA2(acc[2][7],a2,bb); FMA2(acc[3][7],a3,bb); \
            }                                                                \
            __syncthreads();                                                 \
        }                                                                    \
    }

__global__ void __launch_bounds__(256, 2)
kgemm_xv(const float* __restrict__ A, const float* __restrict__ W,
         const float* __restrict__ bias) {
    extern __shared__ float sm[];
    float* As = sm;
    float* Bs = sm + Dm*AS_STRIDE;
    int t = threadIdx.x;
    int m0 = blockIdx.x * 64;
    int tx = t & 31, ty = t >> 5;
    GEMM_STAGE_A(A);
    GEMM_MAIN(W);
    float4 q1 = *(const float4*)(bias + tx*4);
    float4 q2 = *(const float4*)(bias + 128 + tx*4);
    #pragma unroll
    for (int i2 = 0; i2 < 4; i2++) {
        size_t ra = (size_t)(m0 + ty*8 + 2*i2);
        float2 f0 = up2(acc[i2][0]), f1 = up2(acc[i2][1]);
        float2 f2 = up2(acc[i2][2]), f3 = up2(acc[i2][3]);
        float4 oa = {f0.x+q1.x, f1.x+q1.y, f2.x+q1.z, f3.x+q1.w};
        float4 ob = {f0.y+q1.x, f1.y+q1.y, f2.y+q1.z, f3.y+q1.w};
        *(float4*)(g_xv + ra*Dm + tx*4)     = oa;
        *(float4*)(g_xv + (ra+1)*Dm + tx*4) = ob;
        f0 = up2(acc[i2][4]); f1 = up2(acc[i2][5]);
        f2 = up2(acc[i2][6]); f3 = up2(acc[i2][7]);
        float4 oc = {f0.x+q2.x, f1.x+q2.y, f2.x+q2.z, f3.x+q2.w};
        float4 od = {f0.y+q2.x, f1.y+q2.y, f2.y+q2.z, f3.y+q2.w};
        *(float4*)(g_xv + ra*Dm + 128 + tx*4)     = oc;
        *(float4*)(g_xv + (ra+1)*Dm + 128 + tx*4) = od;
    }
}

__global__ void __launch_bounds__(256, 2)
kattn(const float* __restrict__ Z) {
    extern __shared__ float sm[];
    float* As = sm;
    float* Bs = sm + Dm*AS_STRIDE;
    int t = threadIdx.x;
    int m0 = blockIdx.x * 64;
    int tx = t & 31, ty = t >> 5;
    GEMM_STAGE_A(Z);
    GEMM_MAIN(g_WK);
    float4 k1 = *(const float4*)(g_bK + tx*4);
    float4 k2 = *(const float4*)(g_bK + 128 + tx*4);
    #pragma unroll
    for (int i2 = 0; i2 < 4; i2++) {
        size_t ra = (size_t)(m0 + ty*8 + 2*i2);
        float2 f0 = up2(acc[i2][0]), f1 = up2(acc[i2][1]);
        float2 f2 = up2(acc[i2][2]), f3 = up2(acc[i2][3]);
        float ea0 = __expf(f0.x+k1.x), eb0 = __expf(f0.y+k1.x);
        float ea1 = __expf(f1.x+k1.y), eb1 = __expf(f1.y+k1.y);
        float ea2 = __expf(f2.x+k1.z), eb2 = __expf(f2.y+k1.z);
        float ea3 = __expf(f3.x+k1.w), eb3 = __expf(f3.y+k1.w);
        f0 = up2(acc[i2][4]); f1 = up2(acc[i2][5]);
        f2 = up2(acc[i2][6]); f3 = up2(acc[i2][7]);
        float ec0 = __expf(f0.x+k2.x), ed0 = __expf(f0.y+k2.x);
        float ec1 = __expf(f1.x+k2.y), ed1 = __expf(f1.y+k2.y);
        float ec2 = __expf(f2.x+k2.z), ed2 = __expf(f2.y+k2.z);
        float ec3 = __expf(f3.x+k2.w), ed3 = __expf(f3.y+k2.w);
        float sA = ea0+ea1+ea2+ea3, sB = eb0+eb1+eb2+eb3;
        float sC = ec0+ec1+ec2+ec3, sD = ed0+ed1+ed2+ed3;
        #pragma unroll
        for (int m = 1; m <= 8; m <<= 1) {
            sA += __shfl_xor_sync(0xffffffffu, sA, m);
            sB += __shfl_xor_sync(0xffffffffu, sB, m);
            sC += __shfl_xor_sync(0xffffffffu, sC, m);
            sD += __shfl_xor_sync(0xffffffffu, sD, m);
        }
        float iA = __fdividef(1.f, sA), iB = __fdividef(1.f, sB);
        float iC = __fdividef(1.f, sC), iD = __fdividef(1.f, sD);
        float4 oa = {ea0*iA, ea1*iA, ea2*iA, ea3*iA};
        float4 ob = {eb0*iB, eb1*iB, eb2*iB, eb3*iB};
        float4 oc = {ec0*iC, ec1*iC, ec2*iC, ec3*iC};
        float4 od = {ed0*iD, ed1*iD, ed2*iD, ed3*iD};
        *(float4*)(g_e + ra*Dm + tx*4)           = oa;
        *(float4*)(g_e + (ra+1)*Dm + tx*4)       = ob;
        *(float4*)(g_e + ra*Dm + 128 + tx*4)     = oc;
        *(float4*)(g_e + (ra+1)*Dm + 128 + tx*4) = od;
        if ((tx & 15) == 0) {
            int hh = tx >> 4;
            g_rs[ra*Hh + hh]         = sA;
            g_rs[(ra+1)*Hh + hh]     = sB;
            g_rs[ra*Hh + 2 + hh]     = sC;
            g_rs[(ra+1)*Hh + 2 + hh] = sD;
        }
    }
}

__global__ void kpool() {
    __shared__ float Es[64][68];
    __shared__ float Xs[64][68];
    __shared__ float rsv[64];
    int t = threadIdx.x;
    int ch = blockIdx.x, h = blockIdx.y, b = blockIdx.z;
    int r0 = (t >> 4)*4, d0 = (t & 15)*4;
    int lrow = t >> 4, lcol = (t & 15)*4;
    u64 pa[4][2] = {};
    float Sacc = 0.f;
    for (int st = 0; st < 8; st++) {
        int n0 = ch*512 + st*64;
        size_t base = ((size_t)(b*Nn + n0))*Dm + h*64;
        if (t < 64) rsv[t] = g_rs[((size_t)(b*Nn + n0 + t))*Hh + h];
        #pragma unroll
        for (int p = 0; p < 4; p++) {
            int row = lrow + p*16;
            *(float4*)&Es[row][lcol] = *(const float4*)(g_e  + base + (size_t)row*Dm + lcol);
            *(float4*)&Xs[row][lcol] = *(const float4*)(g_xv + base + (size_t)row*Dm + lcol);
        }
        __syncthreads();
        if (t < 64) {
            float s = 0.f;
            #pragma unroll 8
            for (int n = 0; n < 64; n++) s += Es[n][t]*rsv[n];
            Sacc += s;
        }
        #pragma unroll 4
        for (int n = 0; n < 64; n++) {
            float4 a = *(const float4*)&Es[n][r0];
            ulonglong2 x0 = *(const ulonglong2*)&Xs[n][d0];
            u64 aa;
            aa = pk2(a.x,a.x); FMA2(pa[0][0],aa,x0.x); FMA2(pa[0][1],aa,x0.y);
            aa = pk2(a.y,a.y); FMA2(pa[1][0],aa,x0.x); FMA2(pa[1][1],aa,x0.y);
            aa = pk2(a.z,a.z); FMA2(pa[2][0],aa,x0.x); FMA2(pa[2][1],aa,x0.y);
            aa = pk2(a.w,a.w); FMA2(pa[3][0],aa,x0.x); FMA2(pa[3][1],aa,x0.y);
        }
        __syncthreads();
    }
    float* pp = g_pool + ((size_t)(b*Hh + h)*Rr)*HDd;
    #pragma unroll
    for (int i = 0; i < 4; i++) {
        float2 f0 = up2(pa[i][0]), f1 = up2(pa[i][1]);
        float* row = pp + (size_t)(r0 + i)*HDd + d0;
        atomicAdd(row+0, f0.x); atomicAdd(row+1, f0.y);
        atomicAdd(row+2, f1.x); atomicAdd(row+3, f1.y);
    }
    if (t < 64) atomicAdd(&g_S[(b*Hh + h)*Rr + t], Sacc);
}

__global__ void kfin() {
    int i = blockIdx.x*256 + threadIdx.x;
    float inv = 1.f / g_S[i];
    float4* p = (float4*)(g_pool + (size_t)i*HDd);
    #pragma unroll
    for (int d4 = 0; d4 < 16; d4++) {
        float4 v = p[d4];
        v.x *= inv; v.y *= inv; v.z *= inv; v.w *= inv;
        p[d4] = v;
    }
}

#define STR 260
#define SMEM_OUT ((2*64*STR + Hh*Rr*HDd)*4)
__global__ void kout(const float* __restrict__ alpha, const float* __restrict__ beta,
                     float* __restrict__ out) {
    extern __shared__ float sm[];
    float* Es  = sm;
    float* XVs = sm + 64*STR;
    float* P2  = sm + 2*64*STR;
    int t = threadIdx.x;
    int tile = blockIdx.x;
    int b = tile / (Nn/64);
    int n0 = (tile % (Nn/64)) * 64;
    size_t base = ((size_t)b*Nn + n0) * Dm;
    #pragma unroll
    for (int p = 0; p < 16; p++) {
        int idx = t + p*256;
        int row = idx >> 6, c4 = idx & 63;
        *(float4*)&Es [row*STR + c4*4] = *(const float4*)(g_e  + base + (size_t)row*Dm + c4*4);
        *(float4*)&XVs[row*STR + c4*4] = *(const float4*)(g_xv + base + (size_t)row*Dm + c4*4);
    }
    #pragma unroll
    for (int p = 0; p < 16; p++) {
        int idx = t + p*256;
        *(float4*)&P2[idx*4] = *(const float4*)(g_pool + (size_t)b*(Hh*Rr*HDd) + idx*4);
    }
    __syncthreads();
    int n = t & 63, h = t >> 6;
    u64 acc2[32] = {};                       // acc2[k] = cols {2k, 2k+1}
    const float* Erow = Es + n*STR + h*64;
    const float* Ph = P2 + h*Rr*HDd;
    for (int r = 0; r < Rr; r++) {
        float e = Erow[r];
        u64 ee = pk2(e, e);
        const ulonglong2* pr = (const ulonglong2*)(Ph + r*HDd);
        #pragma unroll
        for (int q = 0; q < 16; q++) {       // 16 x 16B = 64 cols
            ulonglong2 pv = pr[q];
            FMA2(acc2[q*2],   ee, pv.x);
            FMA2(acc2[q*2+1], ee, pv.y);
        }
    }
    float rsn = g_rs[((size_t)(b*Nn + n0 + n))*Hh + h];
    float sa = 1.f / (1.f + __expf(-alpha[h]));
    float sb = rsn / (1.f + __expf(-beta[h]));
    float* op = out + base + (size_t)n*Dm + h*64;
    const float* xvp = XVs + n*STR + h*64;
    #pragma unroll
    for (int g = 0; g < 16; g++) {           // 4 cols per group
        float2 f0 = up2(acc2[g*2]), f1 = up2(acc2[g*2+1]);
        float4 o;
        o.x = fmaf(sa, xvp[g*4+0], sb*f0.x);
        o.y = fmaf(sa, xvp[g*4+1], sb*f0.y);
        o.z = fmaf(sa, xvp[g*4+2], sb*f1.x);
        o.w = fmaf(sa, xvp[g*4+3], sb*f1.y);
        *(float4*)(op + g*4) = o;
    }
}

extern "C" void kernel_launch(void* const* d_in, const int* in_sizes, int n_in,
                              void* d_out, int out_size) {
    const float* x     = (const float*)d_in[0];
    const float* z     = (const float*)d_in[1];
    const float* Wq    = (const float*)d_in[2];
    const float* bq    = (const float*)d_in[3];
    const float* K     = (const float*)d_in[4];
    const float* Wv    = (const float*)d_in[5];
    const float* bv    = (const float*)d_in[6];
    const float* alpha = (const float*)d_in[7];
    const float* beta  = (const float*)d_in[8];
    float* out = (float*)d_out;

    cudaFuncSetAttribute(kgemm_xv, cudaFuncAttributeMaxDynamicSharedMemorySize, SMEM_GEMM);
    cudaFuncSetAttribute(kattn,    cudaFuncAttributeMaxDynamicSharedMemorySize, SMEM_GEMM);
    cudaFuncSetAttribute(kout,     cudaFuncAttributeMaxDynamicSharedMemorySize, SMEM_OUT);

    kzero<<<512, 256>>>();
    kprep<<<Dm + 1, 256>>>(Wq, bq, K);
    kgemm_xv<<<Mm/64, 256, SMEM_GEMM>>>(x, Wv, bv);
    kattn<<<Mm/64, 256, SMEM_GEMM>>>(z);
    kpool<<<dim3(16, Hh, Bz), 256>>>();
    kfin<<<Bz*Hh*Rr/256, 256>>>();
    kout<<<Mm/64, 256, SMEM_OUT>>>(alpha, beta, out);
}

// round 5
// speedup vs baseline: 1.8721x; 1.3464x over previous
#include <cuda_runtime.h>
#include <cuda_bf16.h>
#include <cstdint>

#define Bz  8
#define Nn  8192
#define Dm  256
#define Hh  4
#define Rr  64
#define HDd 64
#define Mm  (Bz*Nn)

typedef unsigned long long u64;

// ---------------- device scratch ----------------
__device__ float g_WK[Dm*Dm];
__device__ float g_bK[Dm];
__device__ float g_xv[(size_t)Mm*Dm];
__device__ float g_e [(size_t)Mm*Dm];          // RAW exp(attn)
__device__ float g_rs[(size_t)Mm*Hh];          // per-(n,h) rowsum of e
__device__ float g_pool[Bz*Hh*Rr*HDd];
__device__ float g_S [Bz*Hh*Rr];
__device__ __nv_bfloat16 g_Wh[2][Dm*Dm];       // bf16 hi image of W ([k][n])
__device__ __nv_bfloat16 g_Wl[2][Dm*Dm];       // bf16 lo image

// ---------------- helpers ----------------
__device__ __forceinline__ u64 pk2(float x, float y) {
    u64 r; asm("mov.b64 %0, {%1,%2};" : "=l"(r) : "f"(x), "f"(y)); return r;
}
__device__ __forceinline__ float2 up2(u64 v) {
    float2 f; asm("mov.b64 {%0,%1}, %2;" : "=f"(f.x), "=f"(f.y) : "l"(v)); return f;
}
#define FMA2(d,a,b) asm("fma.rn.f32x2 %0, %1, %2, %0;" : "+l"(d) : "l"(a), "l"(b))

__device__ __forceinline__ void cpa16(uint32_t d, const void* s) {
    asm volatile("cp.async.cg.shared.global [%0], [%1], 16;" :: "r"(d), "l"(s));
}
#define CPCOMMIT() asm volatile("cp.async.commit_group;")
#define CPWAIT0()  asm volatile("cp.async.wait_group 0;")

__device__ __forceinline__ void ldsm4(uint32_t* r, uint32_t a) {
    asm volatile("ldmatrix.sync.aligned.m8n8.x4.shared.b16 {%0,%1,%2,%3}, [%4];"
        : "=r"(r[0]), "=r"(r[1]), "=r"(r[2]), "=r"(r[3]) : "r"(a));
}
__device__ __forceinline__ void ldsm4t(uint32_t* r, uint32_t a) {
    asm volatile("ldmatrix.sync.aligned.m8n8.x4.trans.shared.b16 {%0,%1,%2,%3}, [%4];"
        : "=r"(r[0]), "=r"(r[1]), "=r"(r[2]), "=r"(r[3]) : "r"(a));
}
__device__ __forceinline__ void hmma(float* c, const uint32_t* a, uint32_t b0, uint32_t b1) {
    asm volatile("mma.sync.aligned.m16n8k16.row.col.f32.bf16.bf16.f32 "
        "{%0,%1,%2,%3}, {%4,%5,%6,%7}, {%8,%9}, {%0,%1,%2,%3};"
        : "+f"(c[0]), "+f"(c[1]), "+f"(c[2]), "+f"(c[3])
        : "r"(a[0]), "r"(a[1]), "r"(a[2]), "r"(a[3]), "r"(b0), "r"(b1));
}

// ---------------- small kernels ----------------
__global__ void kzero() {
    int i = blockIdx.x*blockDim.x + threadIdx.x;
    if (i < Bz*Hh*Rr*HDd) g_pool[i] = 0.f;
    if (i < Bz*Hh*Rr)     g_S[i]   = 0.f;
}

__global__ void kprep(const float* __restrict__ Wq, const float* __restrict__ bq,
                      const float* __restrict__ K) {
    int col = threadIdx.x;
    int h = col >> 6, r = col & 63;
    const float* Krow = K + r*Dm + h*HDd;
    if (blockIdx.x < Dm) {
        int c = blockIdx.x;
        const float* wq = Wq + c*Dm + h*HDd;
        float s = 0.f;
        #pragma unroll 16
        for (int d = 0; d < HDd; d++) s = fmaf(wq[d], Krow[d], s);
        g_WK[c*Dm + col] = 0.125f * s;
    } else {
        float s = 0.f;
        #pragma unroll 16
        for (int d = 0; d < HDd; d++) s = fmaf(bq[h*HDd + d], Krow[d], s);
        g_bK[col] = 0.125f * s;
    }
}

// split W into bf16 hi/lo images ([k][n] row-major)
__global__ void kprep2(const float* __restrict__ Wv) {
    int g = blockIdx.y, k = blockIdx.x, n = threadIdx.x;
    float wv = g ? g_WK[k*Dm + n] : Wv[(size_t)k*Dm + n];
    __nv_bfloat16 hi = __float2bfloat16(wv);
    float lo = wv - __bfloat162float(hi);
    g_Wh[g][k*Dm + n] = hi;
    g_Wl[g][k*Dm + n] = __float2bfloat16(lo);
}

// ---------------- HMMA GEMM: C[128,128] per CTA, K=256 (4 chunks of 64) ----------------
// smem: Ah[128][72] bf16 @0 (18432), Al @18432, Bh[64][136] @36864 (17408), Bl @54272
// C fp32 [128][132] aliases @0 after mainloop.
#define AH_OFF 0
#define AL_OFF 18432
#define BH_OFF 36864
#define BL_OFF 54272
#define SMEM_MMA 71680

__global__ void __launch_bounds__(256, 2)
kgemm_mma(const float* __restrict__ A, const float* __restrict__ bias, int gemm) {
    extern __shared__ char sm[];
    uint32_t smb = (uint32_t)__cvta_generic_to_shared(sm);
    const int t = threadIdx.x, w = t >> 5, lane = t & 31;
    const int m0 = blockIdx.x*128, nh = blockIdx.y;
    const __nv_bfloat16* Wh = g_Wh[gemm];
    const __nv_bfloat16* Wl = g_Wl[gemm];
    const float* bp = gemm ? g_bK : bias;

    float acc[2][8][4];
    #pragma unroll
    for (int i = 0; i < 2; i++)
        #pragma unroll
        for (int j = 0; j < 8; j++)
            #pragma unroll
            for (int q = 0; q < 4; q++) acc[i][j][q] = 0.f;

    const int wm = (w >> 1)*32, wn = (w & 1)*64;
    // ldmatrix per-thread base byte offsets
    uint32_t aoff = smb + AH_OFF + (uint32_t)((wm + (lane & 15))*144) + (lane >> 4)*16;
    uint32_t boff = smb + BH_OFF + (uint32_t)((lane & 15)*272) + (uint32_t)((wn + (lane >> 4)*8)*2);

    for (int kc = 0; kc < 4; kc++) {
        // stage B hi/lo via cp.async
        {
            const __nv_bfloat16* srcH = Wh + (size_t)(kc*64)*Dm + nh*128;
            const __nv_bfloat16* srcL = Wl + (size_t)(kc*64)*Dm + nh*128;
            #pragma unroll
            for (int p = 0; p < 4; p++) {
                int idx = t + p*256;
                int row = idx >> 4, seg = idx & 15;
                uint32_t d = smb + BH_OFF + (uint32_t)(row*272 + seg*16);
                cpa16(d, srcH + (size_t)row*Dm + seg*8);
                cpa16(d + (BL_OFF - BH_OFF), srcL + (size_t)row*Dm + seg*8);
            }
            CPCOMMIT();
        }
        // stage A: fp32 -> bf16 hi/lo
        {
            int row = t >> 1, kq = (t & 1)*32;
            const float4* ar = (const float4*)(A + (size_t)(m0 + row)*Dm + kc*64 + kq);
            char* wbH = sm + AH_OFF + row*144 + kq*2;
            char* wbL = sm + AL_OFF + row*144 + kq*2;
            #pragma unroll
            for (int j4 = 0; j4 < 8; j4++) {
                float4 v = ar[j4];
                uint32_t h01, h23, q01, q23;
                asm("cvt.rn.bf16x2.f32 %0, %1, %2;" : "=r"(h01) : "f"(v.y), "f"(v.x));
                asm("cvt.rn.bf16x2.f32 %0, %1, %2;" : "=r"(h23) : "f"(v.w), "f"(v.z));
                float l0 = v.x - __uint_as_float(h01 << 16);
                float l1 = v.y - __uint_as_float(h01 & 0xffff0000u);
                float l2 = v.z - __uint_as_float(h23 << 16);
                float l3 = v.w - __uint_as_float(h23 & 0xffff0000u);
                asm("cvt.rn.bf16x2.f32 %0, %1, %2;" : "=r"(q01) : "f"(l1), "f"(l0));
                asm("cvt.rn.bf16x2.f32 %0, %1, %2;" : "=r"(q23) : "f"(l3), "f"(l2));
                *(uint2*)(wbH + j4*8) = make_uint2(h01, h23);
                *(uint2*)(wbL + j4*8) = make_uint2(q01, q23);
            }
        }
        CPWAIT0();
        __syncthreads();

        // compute: 4 k16-steps, 3 products each
        #pragma unroll
        for (int ks = 0; ks < 4; ks++) {
            uint32_t ah[2][4], al[2][4];
            uint32_t ab = aoff + ks*32;
            ldsm4(ah[0], ab);
            ldsm4(ah[1], ab + 16*144);
            ldsm4(al[0], ab + (AL_OFF - AH_OFF));
            ldsm4(al[1], ab + (AL_OFF - AH_OFF) + 16*144);
            uint32_t bb = boff + ks*16*272;
            #pragma unroll
            for (int nq = 0; nq < 4; nq++) {
                uint32_t bh[4], bl[4];
                ldsm4t(bh, bb + nq*32);
                ldsm4t(bl, bb + nq*32 + (BL_OFF - BH_OFF));
                #pragma unroll
                for (int mt = 0; mt < 2; mt++) {
                    #pragma unroll
                    for (int sub = 0; sub < 2; sub++) {
                        float* c = acc[mt][nq*2 + sub];
                        hmma(c, ah[mt], bh[sub*2], bh[sub*2+1]);
                        hmma(c, al[mt], bh[sub*2], bh[sub*2+1]);
                        hmma(c, ah[mt], bl[sub*2], bl[sub*2+1]);
                    }
                }
            }
        }
        __syncthreads();
    }

    // stage C through smem for coalesced epilogue
    float* Cs = (float*)sm;
    #pragma unroll
    for (int mt = 0; mt < 2; mt++)
        #pragma unroll
        for (int j = 0; j < 8; j++) {
            int r = wm + mt*16 + (lane >> 2);
            int c = wn + j*8 + (lane & 3)*2;
            *(float2*)&Cs[r*132 + c]       = make_float2(acc[mt][j][0], acc[mt][j][1]);
            *(float2*)&Cs[(r+8)*132 + c]   = make_float2(acc[mt][j][2], acc[mt][j][3]);
        }
    __syncthreads();

    float4 bv4 = *(const float4*)(bp + nh*128 + lane*4);
    if (gemm == 0) {
        #pragma unroll
        for (int p = 0; p < 16; p++) {
            int row = p*8 + w;
            float4 v = *(const float4*)&Cs[row*132 + lane*4];
            v.x += bv4.x; v.y += bv4.y; v.z += bv4.z; v.w += bv4.w;
            *(float4*)(g_xv + (size_t)(m0 + row)*Dm + nh*128 + lane*4) = v;
        }
    } else {
        #pragma unroll
        for (int p = 0; p < 16; p++) {
            int row = p*8 + w;
            float4 v = *(const float4*)&Cs[row*132 + lane*4];
            v.x = __expf(v.x + bv4.x);
            v.y = __expf(v.y + bv4.y);
            v.z = __expf(v.z + bv4.z);
            v.w = __expf(v.w + bv4.w);
            float s = v.x + v.y + v.z + v.w;
            s += __shfl_xor_sync(0xffffffffu, s, 1);
            s += __shfl_xor_sync(0xffffffffu, s, 2);
            s += __shfl_xor_sync(0xffffffffu, s, 4);
            s += __shfl_xor_sync(0xffffffffu, s, 8);
            *(float4*)(g_e + (size_t)(m0 + row)*Dm + nh*128 + lane*4) = v;
            if ((lane & 15) == 0)
                g_rs[(size_t)(m0 + row)*Hh + nh*2 + (lane >> 4)] = s;
        }
    }
}

// ---------------- pooled + S (raw-e formulation) ----------------
__global__ void kpool() {
    __shared__ float Es[64][68];
    __shared__ float Xs[64][68];
    __shared__ float rsv[64];      // 1/rs
    int t = threadIdx.x;
    int ch = blockIdx.x, h = blockIdx.y, b = blockIdx.z;
    int r0 = (t >> 4)*4, d0 = (t & 15)*4;
    int lrow = t >> 4, lcol = (t & 15)*4;
    u64 pa[4][2] = {};
    float Sacc = 0.f;
    for (int st = 0; st < 8; st++) {
        int n0 = ch*512 + st*64;
        size_t base = ((size_t)(b*Nn + n0))*Dm + h*64;
        if (t < 64) rsv[t] = 1.f / g_rs[((size_t)(b*Nn + n0 + t))*Hh + h];
        #pragma unroll
        for (int p = 0; p < 4; p++) {
            int row = lrow + p*16;
            *(float4*)&Es[row][lcol] = *(const float4*)(g_e  + base + (size_t)row*Dm + lcol);
            *(float4*)&Xs[row][lcol] = *(const float4*)(g_xv + base + (size_t)row*Dm + lcol);
        }
        __syncthreads();
        if (t < 64) {
            float s = 0.f;
            #pragma unroll 8
            for (int n = 0; n < 64; n++) s += Es[n][t];   // raw e
            Sacc += s;
        }
        #pragma unroll 4
        for (int n = 0; n < 64; n++) {
            float inv = rsv[n];
            float4 a = *(const float4*)&Es[n][r0];
            ulonglong2 x0 = *(const ulonglong2*)&Xs[n][d0];
            u64 aa; float v;
            v = a.x*inv; aa = pk2(v,v); FMA2(pa[0][0],aa,x0.x); FMA2(pa[0][1],aa,x0.y);
            v = a.y*inv; aa = pk2(v,v); FMA2(pa[1][0],aa,x0.x); FMA2(pa[1][1],aa,x0.y);
            v = a.z*inv; aa = pk2(v,v); FMA2(pa[2][0],aa,x0.x); FMA2(pa[2][1],aa,x0.y);
            v = a.w*inv; aa = pk2(v,v); FMA2(pa[3][0],aa,x0.x); FMA2(pa[3][1],aa,x0.y);
        }
        __syncthreads();
    }
    float* pp = g_pool + ((size_t)(b*Hh + h)*Rr)*HDd;
    #pragma unroll
    for (int i = 0; i < 4; i++) {
        float2 f0 = up2(pa[i][0]), f1 = up2(pa[i][1]);
        float* row = pp + (size_t)(r0 + i)*HDd + d0;
        atomicAdd(row+0, f0.x); atomicAdd(row+1, f0.y);
        atomicAdd(row+2, f1.x); atomicAdd(row+3, f1.y);
    }
    if (t < 64) atomicAdd(&g_S[(b*Hh + h)*Rr + t], Sacc);
}

__global__ void kfin() {
    int i = blockIdx.x*256 + threadIdx.x;
    float inv = 1.f / g_S[i];
    float4* p = (float4*)(g_pool + (size_t)i*HDd);
    #pragma unroll
    for (int d4 = 0; d4 < 16; d4++) {
        float4 v = p[d4];
        v.x *= inv; v.y *= inv; v.z *= inv; v.w *= inv;
        p[d4] = v;
    }
}

// ---------------- redistribute + gated output ----------------
#define STR 260
#define SMEM_OUT ((2*64*STR + Hh*Rr*HDd)*4)
__global__ void kout(const float* __restrict__ alpha, const float* __restrict__ beta,
                     float* __restrict__ out) {
    extern __shared__ float smf[];
    float* Es  = smf;
    float* XVs = smf + 64*STR;
    float* P2  = smf + 2*64*STR;
    int t = threadIdx.x;
    int tile = blockIdx.x;
    int b = tile / (Nn/64);
    int n0 = (tile % (Nn/64)) * 64;
    size_t base = ((size_t)b*Nn + n0) * Dm;
    #pragma unroll
    for (int p = 0; p < 16; p++) {
        int idx = t + p*256;
        int row = idx >> 6, c4 = idx & 63;
        *(float4*)&Es [row*STR + c4*4] = *(const float4*)(g_e  + base + (size_t)row*Dm + c4*4);
        *(float4*)&XVs[row*STR + c4*4] = *(const float4*)(g_xv + base + (size_t)row*Dm + c4*4);
    }
    #pragma unroll
    for (int p = 0; p < 16; p++) {
        int idx = t + p*256;
        *(float4*)&P2[idx*4] = *(const float4*)(g_pool + (size_t)b*(Hh*Rr*HDd) + idx*4);
    }
    __syncthreads();
    int n = t & 63, h = t >> 6;
    u64 acc2[32] = {};
    const float* Erow = Es + n*STR + h*64;
    const float* Ph = P2 + h*Rr*HDd;
    for (int r = 0; r < Rr; r++) {
        float e = Erow[r];
        u64 ee = pk2(e, e);
        const ulonglong2* pr = (const ulonglong2*)(Ph + r*HDd);
        #pragma unroll
        for (int q = 0; q < 16; q++) {
            ulonglong2 pv = pr[q];
            FMA2(acc2[q*2],   ee, pv.x);
            FMA2(acc2[q*2+1], ee, pv.y);
        }
    }
    float sa = 1.f / (1.f + __expf(-alpha[h]));
    float sb = 1.f / (1.f + __expf(-beta[h]));
    float* op = out + base + (size_t)n*Dm + h*64;
    const float* xvp = XVs + n*STR + h*64;
    #pragma unroll
    for (int g = 0; g < 16; g++) {
        float2 f0 = up2(acc2[g*2]), f1 = up2(acc2[g*2+1]);
        float4 o;
        o.x = fmaf(sa, xvp[g*4+0], sb*f0.x);
        o.y = fmaf(sa, xvp[g*4+1], sb*f0.y);
        o.z = fmaf(sa, xvp[g*4+2], sb*f1.x);
        o.w = fmaf(sa, xvp[g*4+3], sb*f1.y);
        *(float4*)(op + g*4) = o;
    }
}

extern "C" void kernel_launch(void* const* d_in, const int* in_sizes, int n_in,
                              void* d_out, int out_size) {
    const float* x     = (const float*)d_in[0];
    const float* z     = (const float*)d_in[1];
    const float* Wq    = (const float*)d_in[2];
    const float* bq    = (const float*)d_in[3];
    const float* K     = (const float*)d_in[4];
    const float* Wv    = (const float*)d_in[5];
    const float* bv    = (const float*)d_in[6];
    const float* alpha = (const float*)d_in[7];
    const float* beta  = (const float*)d_in[8];
    float* out = (float*)d_out;

    cudaFuncSetAttribute(kgemm_mma, cudaFuncAttributeMaxDynamicSharedMemorySize, SMEM_MMA);
    cudaFuncSetAttribute(kout,      cudaFuncAttributeMaxDynamicSharedMemorySize, SMEM_OUT);

    kzero<<<512, 256>>>();
    kprep<<<Dm + 1, 256>>>(Wq, bq, K);
    kprep2<<<dim3(Dm, 2), 256>>>(Wv);
    kgemm_mma<<<dim3(Mm/128, 2), 256, SMEM_MMA>>>(x, bv, 0);
    kgemm_mma<<<dim3(Mm/128, 2), 256, SMEM_MMA>>>(z, bv, 1);
    kpool<<<dim3(16, Hh, Bz), 256>>>();
    kfin<<<Bz*Hh*Rr/256, 256>>>();
    kout<<<Mm/64, 256, SMEM_OUT>>>(alpha, beta, out);
}

// round 6
// speedup vs baseline: 2.4704x; 1.3196x over previous
#include <cuda_runtime.h>
#include <cuda_bf16.h>
#include <cstdint>

#define Bz  8
#define Nn  8192
#define Dm  256
#define Hh  4
#define Rr  64
#define HDd 64
#define Mm  (Bz*Nn)

typedef unsigned long long u64;

// ---------------- device scratch ----------------
__device__ float g_WK[Dm*Dm];
__device__ float g_bK[Dm];
__device__ float g_xv[(size_t)Mm*Dm];                 // fp32 xv (exact gate term)
__device__ __nv_bfloat16 g_eb  [(size_t)Mm*Dm];       // bf16 raw exp(attn)
__device__ __nv_bfloat16 g_xvsb[(size_t)Mm*Dm];       // bf16 xv / rs[n,h]
__device__ float g_rs[(size_t)Mm*Hh];                 // fp32 rowsum of e per (n,h)
__device__ float g_pool[Bz*Hh*Rr*HDd];                // fp32 P0 accumulator
__device__ __nv_bfloat16 g_poolb[Bz*Hh*Rr*HDd];       // bf16 P0/S
__device__ float g_S [Bz*Hh*Rr];
__device__ __nv_bfloat16 g_Wh[2][Dm*Dm];              // bf16 hi image of W ([k][n])
__device__ __nv_bfloat16 g_Wl[2][Dm*Dm];              // bf16 lo image

// ---------------- helpers ----------------
__device__ __forceinline__ void cpa16(uint32_t d, const void* s) {
    asm volatile("cp.async.cg.shared.global [%0], [%1], 16;" :: "r"(d), "l"(s));
}
#define CPCOMMIT() asm volatile("cp.async.commit_group;")
#define CPWAIT0()  asm volatile("cp.async.wait_group 0;")

__device__ __forceinline__ void ldsm4(uint32_t* r, uint32_t a) {
    asm volatile("ldmatrix.sync.aligned.m8n8.x4.shared.b16 {%0,%1,%2,%3}, [%4];"
        : "=r"(r[0]), "=r"(r[1]), "=r"(r[2]), "=r"(r[3]) : "r"(a));
}
__device__ __forceinline__ void ldsm4t(uint32_t* r, uint32_t a) {
    asm volatile("ldmatrix.sync.aligned.m8n8.x4.trans.shared.b16 {%0,%1,%2,%3}, [%4];"
        : "=r"(r[0]), "=r"(r[1]), "=r"(r[2]), "=r"(r[3]) : "r"(a));
}
__device__ __forceinline__ void hmma(float* c, const uint32_t* a, uint32_t b0, uint32_t b1) {
    asm volatile("mma.sync.aligned.m16n8k16.row.col.f32.bf16.bf16.f32 "
        "{%0,%1,%2,%3}, {%4,%5,%6,%7}, {%8,%9}, {%0,%1,%2,%3};"
        : "+f"(c[0]), "+f"(c[1]), "+f"(c[2]), "+f"(c[3])
        : "r"(a[0]), "r"(a[1]), "r"(a[2]), "r"(a[3]), "r"(b0), "r"(b1));
}
__device__ __forceinline__ uint2 f4_to_bf16x4(float4 v) {
    uint32_t a, b;
    asm("cvt.rn.bf16x2.f32 %0, %1, %2;" : "=r"(a) : "f"(v.y), "f"(v.x));
    asm("cvt.rn.bf16x2.f32 %0, %1, %2;" : "=r"(b) : "f"(v.w), "f"(v.z));
    return make_uint2(a, b);
}

// ---------------- small kernels ----------------
__global__ void kzero() {
    int i = blockIdx.x*blockDim.x + threadIdx.x;
    if (i < Bz*Hh*Rr*HDd) g_pool[i] = 0.f;
    if (i < Bz*Hh*Rr)     g_S[i]   = 0.f;
}

__global__ void kprep(const float* __restrict__ Wq, const float* __restrict__ bq,
                      const float* __restrict__ K) {
    int col = threadIdx.x;
    int h = col >> 6, r = col & 63;
    const float* Krow = K + r*Dm + h*HDd;
    if (blockIdx.x < Dm) {
        int c = blockIdx.x;
        const float* wq = Wq + c*Dm + h*HDd;
        float s = 0.f;
        #pragma unroll 16
        for (int d = 0; d < HDd; d++) s = fmaf(wq[d], Krow[d], s);
        g_WK[c*Dm + col] = 0.125f * s;
    } else {
        float s = 0.f;
        #pragma unroll 16
        for (int d = 0; d < HDd; d++) s = fmaf(bq[h*HDd + d], Krow[d], s);
        g_bK[col] = 0.125f * s;
    }
}

__global__ void kprep2(const float* __restrict__ Wv) {
    int g = blockIdx.y, k = blockIdx.x, n = threadIdx.x;
    float wv = g ? g_WK[k*Dm + n] : Wv[(size_t)k*Dm + n];
    __nv_bfloat16 hi = __float2bfloat16(wv);
    float lo = wv - __bfloat162float(hi);
    g_Wh[g][k*Dm + n] = hi;
    g_Wl[g][k*Dm + n] = __float2bfloat16(lo);
}

// ---------------- HMMA GEMM: C[128,128] per CTA, K=256 ----------------
#define AH_OFF 0
#define AL_OFF 18432
#define BH_OFF 36864
#define BL_OFF 54272
#define RS_OFF 67584
#define SMEM_MMA 71680

__global__ void __launch_bounds__(256, 2)
kgemm_mma(const float* __restrict__ A, const float* __restrict__ bias, int gemm) {
    extern __shared__ char sm[];
    uint32_t smb = (uint32_t)__cvta_generic_to_shared(sm);
    const int t = threadIdx.x, w = t >> 5, lane = t & 31;
    const int m0 = blockIdx.x*128, nh = blockIdx.y;
    const __nv_bfloat16* Wh = g_Wh[gemm];
    const __nv_bfloat16* Wl = g_Wl[gemm];
    const float* bp = gemm ? g_bK : bias;

    float acc[2][8][4];
    #pragma unroll
    for (int i = 0; i < 2; i++)
        #pragma unroll
        for (int j = 0; j < 8; j++)
            #pragma unroll
            for (int q = 0; q < 4; q++) acc[i][j][q] = 0.f;

    const int wm = (w >> 1)*32, wn = (w & 1)*64;
    uint32_t aoff = smb + AH_OFF + (uint32_t)((wm + (lane & 15))*144) + (lane >> 4)*16;
    uint32_t boff = smb + BH_OFF + (uint32_t)((lane & 15)*272) + (uint32_t)((wn + (lane >> 4)*8)*2);

    for (int kc = 0; kc < 4; kc++) {
        {
            const __nv_bfloat16* srcH = Wh + (size_t)(kc*64)*Dm + nh*128;
            const __nv_bfloat16* srcL = Wl + (size_t)(kc*64)*Dm + nh*128;
            #pragma unroll
            for (int p = 0; p < 4; p++) {
                int idx = t + p*256;
                int row = idx >> 4, seg = idx & 15;
                uint32_t d = smb + BH_OFF + (uint32_t)(row*272 + seg*16);
                cpa16(d, srcH + (size_t)row*Dm + seg*8);
                cpa16(d + (BL_OFF - BH_OFF), srcL + (size_t)row*Dm + seg*8);
            }
            CPCOMMIT();
        }
        {
            int row = t >> 1, kq = (t & 1)*32;
            const float4* ar = (const float4*)(A + (size_t)(m0 + row)*Dm + kc*64 + kq);
            char* wbH = sm + AH_OFF + row*144 + kq*2;
            char* wbL = sm + AL_OFF + row*144 + kq*2;
            #pragma unroll
            for (int j4 = 0; j4 < 8; j4++) {
                float4 v = ar[j4];
                uint32_t h01, h23, q01, q23;
                asm("cvt.rn.bf16x2.f32 %0, %1, %2;" : "=r"(h01) : "f"(v.y), "f"(v.x));
                asm("cvt.rn.bf16x2.f32 %0, %1, %2;" : "=r"(h23) : "f"(v.w), "f"(v.z));
                float l0 = v.x - __uint_as_float(h01 << 16);
                float l1 = v.y - __uint_as_float(h01 & 0xffff0000u);
                float l2 = v.z - __uint_as_float(h23 << 16);
                float l3 = v.w - __uint_as_float(h23 & 0xffff0000u);
                asm("cvt.rn.bf16x2.f32 %0, %1, %2;" : "=r"(q01) : "f"(l1), "f"(l0));
                asm("cvt.rn.bf16x2.f32 %0, %1, %2;" : "=r"(q23) : "f"(l3), "f"(l2));
                *(uint2*)(wbH + j4*8) = make_uint2(h01, h23);
                *(uint2*)(wbL + j4*8) = make_uint2(q01, q23);
            }
        }
        CPWAIT0();
        __syncthreads();

        #pragma unroll
        for (int ks = 0; ks < 4; ks++) {
            uint32_t ah[2][4], al[2][4];
            uint32_t ab = aoff + ks*32;
            ldsm4(ah[0], ab);
            ldsm4(ah[1], ab + 16*144);
            ldsm4(al[0], ab + (AL_OFF - AH_OFF));
            ldsm4(al[1], ab + (AL_OFF - AH_OFF) + 16*144);
            uint32_t bb = boff + ks*16*272;
            #pragma unroll
            for (int nq = 0; nq < 4; nq++) {
                uint32_t bh[4], bl[4];
                ldsm4t(bh, bb + nq*32);
                ldsm4t(bl, bb + nq*32 + (BL_OFF - BH_OFF));
                #pragma unroll
                for (int mt = 0; mt < 2; mt++) {
                    #pragma unroll
                    for (int sub = 0; sub < 2; sub++) {
                        float* c = acc[mt][nq*2 + sub];
                        hmma(c, ah[mt], bh[sub*2], bh[sub*2+1]);
                        hmma(c, al[mt], bh[sub*2], bh[sub*2+1]);
                        hmma(c, ah[mt], bl[sub*2], bl[sub*2+1]);
                    }
                }
            }
        }
        __syncthreads();
    }

    // stage C through smem
    float* Cs = (float*)sm;
    #pragma unroll
    for (int mt = 0; mt < 2; mt++)
        #pragma unroll
        for (int j = 0; j < 8; j++) {
            int r = wm + mt*16 + (lane >> 2);
            int c = wn + j*8 + (lane & 3)*2;
            *(float2*)&Cs[r*132 + c]       = make_float2(acc[mt][j][0], acc[mt][j][1]);
            *(float2*)&Cs[(r+8)*132 + c]   = make_float2(acc[mt][j][2], acc[mt][j][3]);
        }
    float* rsS = (float*)(sm + RS_OFF);
    if (gemm == 0 && t < 128)
        *(float2*)&rsS[t*2] = *(const float2*)(g_rs + (size_t)(m0 + t)*Hh + nh*2);
    __syncthreads();

    float4 bv4 = *(const float4*)(bp + nh*128 + lane*4);
    if (gemm == 0) {
        #pragma unroll
        for (int p = 0; p < 16; p++) {
            int row = p*8 + w;
            float4 v = *(const float4*)&Cs[row*132 + lane*4];
            v.x += bv4.x; v.y += bv4.y; v.z += bv4.z; v.w += bv4.w;
            *(float4*)(g_xv + (size_t)(m0 + row)*Dm + nh*128 + lane*4) = v;
            float inv = 1.f / rsS[row*2 + (lane >> 4)];
            float4 s = {v.x*inv, v.y*inv, v.z*inv, v.w*inv};
            *(uint2*)(g_xvsb + (size_t)(m0 + row)*Dm + nh*128 + lane*4) = f4_to_bf16x4(s);
        }
    } else {
        #pragma unroll
        for (int p = 0; p < 16; p++) {
            int row = p*8 + w;
            float4 v = *(const float4*)&Cs[row*132 + lane*4];
            v.x = __expf(v.x + bv4.x);
            v.y = __expf(v.y + bv4.y);
            v.z = __expf(v.z + bv4.z);
            v.w = __expf(v.w + bv4.w);
            float s = v.x + v.y + v.z + v.w;
            s += __shfl_xor_sync(0xffffffffu, s, 1);
            s += __shfl_xor_sync(0xffffffffu, s, 2);
            s += __shfl_xor_sync(0xffffffffu, s, 4);
            s += __shfl_xor_sync(0xffffffffu, s, 8);
            *(uint2*)(g_eb + (size_t)(m0 + row)*Dm + nh*128 + lane*4) = f4_to_bf16x4(v);
            if ((lane & 15) == 0)
                g_rs[(size_t)(m0 + row)*Hh + nh*2 + (lane >> 4)] = s;
        }
    }
}

// ---------------- kpool: P0[r,d] = sum_n e_bf * xvs_bf  (HMMA) ----------------
// E tile [64 n][64 r] bf16 stride 144B; XVS tile same. A = E^T via ldsm4t.
__global__ void __launch_bounds__(256, 4) kpool() {
    __shared__ char smE[64*144];
    __shared__ char smX[64*144];
    uint32_t sE = (uint32_t)__cvta_generic_to_shared(smE);
    uint32_t sX = (uint32_t)__cvta_generic_to_shared(smX);
    const int t = threadIdx.x, w = t >> 5, lane = t & 31;
    const int ch = blockIdx.x, h = blockIdx.y, b = blockIdx.z;
    const int r_base = (w & 3)*16, d_base = (w >> 2)*32;
    float acc[4][4];
    #pragma unroll
    for (int i = 0; i < 4; i++)
        #pragma unroll
        for (int q = 0; q < 4; q++) acc[i][q] = 0.f;
    float Sacc = 0.f;

    // A frag addresses (E^T): row = ks*16 + ((lane>>4)<<3) + (lane&7); col = r_base + ((lane>>3)&1)*8
    uint32_t aoff = sE + (uint32_t)((((lane >> 4) << 3) + (lane & 7))*144)
                  + (uint32_t)((r_base + (((lane >> 3) & 1) << 3))*2);
    uint32_t boff = sX + (uint32_t)((lane & 15)*144) + (uint32_t)((d_base + (lane >> 4)*8)*2);

    for (int tile = 0; tile < 16; tile++) {
        int n0 = ch*1024 + tile*64;
        size_t gbase = ((size_t)(b*Nn + n0))*Dm + h*64;
        #pragma unroll
        for (int p = 0; p < 2; p++) {
            int c = t + p*256;
            int row = c >> 3, off = c & 7;
            cpa16(sE + row*144 + off*16, g_eb   + gbase + (size_t)row*Dm + off*8);
            cpa16(sX + row*144 + off*16, g_xvsb + gbase + (size_t)row*Dm + off*8);
        }
        CPCOMMIT();
        CPWAIT0();
        __syncthreads();

        if (t < 64) {
            const __nv_bfloat16* Eb = (const __nv_bfloat16*)smE;
            float s = 0.f;
            #pragma unroll 8
            for (int n = 0; n < 64; n++) s += __bfloat162float(Eb[n*72 + t]);
            Sacc += s;
        }
        #pragma unroll
        for (int ks = 0; ks < 4; ks++) {
            uint32_t a[4];
            ldsm4t(a, aoff + ks*16*144);
            #pragma unroll
            for (int dq = 0; dq < 2; dq++) {
                uint32_t bf[4];
                ldsm4t(bf, boff + ks*16*144 + dq*32);
                hmma(acc[dq*2],   a, bf[0], bf[1]);
                hmma(acc[dq*2+1], a, bf[2], bf[3]);
            }
        }
        __syncthreads();
    }
    float* pp = g_pool + ((size_t)(b*Hh + h)*Rr)*HDd;
    #pragma unroll
    for (int i = 0; i < 4; i++) {
        int r = r_base + (lane >> 2);
        int d = d_base + i*8 + (lane & 3)*2;
        atomicAdd(&pp[r*HDd + d],       acc[i][0]);
        atomicAdd(&pp[r*HDd + d + 1],   acc[i][1]);
        atomicAdd(&pp[(r+8)*HDd + d],   acc[i][2]);
        atomicAdd(&pp[(r+8)*HDd + d+1], acc[i][3]);
    }
    if (t < 64) atomicAdd(&g_S[(b*Hh + h)*Rr + t], Sacc);
}

// ---------------- kfin: poolb = bf16(P0 / S) ----------------
__global__ void kfin() {
    int row = blockIdx.x*256 + threadIdx.x;     // 2048 (b,h,r) rows
    float inv = 1.f / g_S[row];
    const float4* p = (const float4*)(g_pool + (size_t)row*HDd);
    uint2* q = (uint2*)(g_poolb + (size_t)row*HDd);
    #pragma unroll
    for (int i = 0; i < 16; i++) {
        float4 v = p[i];
        v.x *= inv; v.y *= inv; v.z *= inv; v.w *= inv;
        q[i] = f4_to_bf16x4(v);
    }
}

// ---------------- kout: out = sa*xv + sb*(E · P)  (HMMA per head) ----------------
#define KO_E  0                  // 64 rows x 528B
#define KO_P  33792              // 256 rows x 144B
#define SMEM_KOUT 70656
__global__ void __launch_bounds__(256)
kout(const float* __restrict__ alpha, const float* __restrict__ beta,
     float* __restrict__ out) {
    extern __shared__ char sm[];
    uint32_t smb = (uint32_t)__cvta_generic_to_shared(sm);
    const int t = threadIdx.x, w = t >> 5, lane = t & 31;
    const int b = blockIdx.x >> 7;
    const int n0 = (blockIdx.x & 127)*64;
    const int hw = w & 3, m_base = (w >> 2)*32;
    size_t gbase = ((size_t)(b*Nn + n0))*Dm;

    // stage E (64 x 256 bf16) and P (4 heads x 64 x 64 bf16)
    #pragma unroll
    for (int p = 0; p < 8; p++) {
        int c = t + p*256;
        int row = c >> 5, off = c & 31;
        cpa16(smb + KO_E + row*528 + off*16, g_eb + gbase + (size_t)row*Dm + off*8);
        int prow = c >> 3, poff = c & 7;
        cpa16(smb + KO_P + prow*144 + poff*16,
              g_poolb + (size_t)b*(Hh*Rr*HDd) + prow*64 + poff*8);
    }
    CPCOMMIT();
    CPWAIT0();
    __syncthreads();

    float acc[2][8][4];
    #pragma unroll
    for (int i = 0; i < 2; i++)
        #pragma unroll
        for (int j = 0; j < 8; j++)
            #pragma unroll
            for (int q = 0; q < 4; q++) acc[i][j][q] = 0.f;

    uint32_t aoff = smb + KO_E + (uint32_t)((m_base + (lane & 15))*528)
                  + (uint32_t)(hw*128) + (lane >> 4)*16;
    uint32_t boff = smb + KO_P + (uint32_t)(hw*9216)
                  + (uint32_t)((lane & 15)*144) + (uint32_t)((lane >> 4)*16);

    #pragma unroll
    for (int ks = 0; ks < 4; ks++) {
        uint32_t a0[4], a1[4];
        ldsm4(a0, aoff + ks*32);
        ldsm4(a1, aoff + ks*32 + 16*528);
        #pragma unroll
        for (int dq = 0; dq < 4; dq++) {
            uint32_t bf[4];
            ldsm4t(bf, boff + ks*16*144 + dq*32);
            hmma(acc[0][dq*2],   a0, bf[0], bf[1]);
            hmma(acc[0][dq*2+1], a0, bf[2], bf[3]);
            hmma(acc[1][dq*2],   a1, bf[0], bf[1]);
            hmma(acc[1][dq*2+1], a1, bf[2], bf[3]);
        }
    }

    float sa = 1.f / (1.f + __expf(-alpha[hw]));
    float sb = 1.f / (1.f + __expf(-beta[hw]));
    #pragma unroll
    for (int mt = 0; mt < 2; mt++)
        #pragma unroll
        for (int j = 0; j < 8; j++) {
            int row = m_base + mt*16 + (lane >> 2);
            int col = hw*64 + j*8 + (lane & 3)*2;
            const float* c = acc[mt][j];
            {
                float2 xv = *(const float2*)(g_xv + gbase + (size_t)row*Dm + col);
                float2 o = {fmaf(sa, xv.x, sb*c[0]), fmaf(sa, xv.y, sb*c[1])};
                *(float2*)(out + gbase + (size_t)row*Dm + col) = o;
            }
            {
                float2 xv = *(const float2*)(g_xv + gbase + (size_t)(row+8)*Dm + col);
                float2 o = {fmaf(sa, xv.x, sb*c[2]), fmaf(sa, xv.y, sb*c[3])};
                *(float2*)(out + gbase + (size_t)(row+8)*Dm + col) = o;
            }
        }
}

extern "C" void kernel_launch(void* const* d_in, const int* in_sizes, int n_in,
                              void* d_out, int out_size) {
    const float* x     = (const float*)d_in[0];
    const float* z     = (const float*)d_in[1];
    const float* Wq    = (const float*)d_in[2];
    const float* bq    = (const float*)d_in[3];
    const float* K     = (const float*)d_in[4];
    const float* Wv    = (const float*)d_in[5];
    const float* bv    = (const float*)d_in[6];
    const float* alpha = (const float*)d_in[7];
    const float* beta  = (const float*)d_in[8];
    float* out = (float*)d_out;

    cudaFuncSetAttribute(kgemm_mma, cudaFuncAttributeMaxDynamicSharedMemorySize, SMEM_MMA);
    cudaFuncSetAttribute(kout,      cudaFuncAttributeMaxDynamicSharedMemorySize, SMEM_KOUT);

    kzero<<<512, 256>>>();
    kprep<<<Dm + 1, 256>>>(Wq, bq, K);
    kprep2<<<dim3(Dm, 2), 256>>>(Wv);
    kgemm_mma<<<dim3(Mm/128, 2), 256, SMEM_MMA>>>(z, bv, 1);   // attn first (produces rs)
    kgemm_mma<<<dim3(Mm/128, 2), 256, SMEM_MMA>>>(x, bv, 0);   // xv + xvs (needs rs)
    kpool<<<dim3(8, Hh, Bz), 256>>>();
    kfin<<<8, 256>>>();
    kout<<<Mm/64, 256, SMEM_KOUT>>>(alpha, beta, out);
}